// round 12
// baseline (speedup 1.0000x reference)
#include <cuda_runtime.h>
#include <cstdint>
#include <cfloat>

// VectorQuantizer on B200 — round 12: single-pass HMMA with per-thread best-3
// tracking (pass 2 deleted). Exact-fp32 recheck keeps indices bit-identical.
#define KCODES    512
#define DCH       64
#define SPATIAL   32768
#define NVEC      262144
#define Q_ELEMS   16777216
#define LOSS_OFF  Q_ELEMS
#define IDX_OFF   (Q_ELEMS + 1)
#define TILE_M    64
#define NTILES    (NVEC / TILE_M)   // 4096
#define GRID_MAIN 296               // 2 CTAs per SM
#define BLOCK_MAIN 128
#define MARGIN    3e-3f

#define A_STRIDE   144
#define B_STRIDE   144
#define XF_STRIDE  68               // floats
#define SM_A       0                // 9216
#define SM_B       9216             // 73728
#define SM_XF      82944            // 17408
#define SM_SSC     100352           // 2048
#define SM_SXS     102400           // 256
#define SM_BIDX    102656           // 256
#define SM_LOSS    102912           // 16
#define SM_TOTAL   102944

__device__ double g_blocksums[GRID_MAIN];

__device__ __forceinline__ uint32_t smem_u32(const void* p) {
    uint32_t a;
    asm("{ .reg .u64 t; cvta.to.shared.u64 t, %1; cvt.u32.u64 %0, t; }" : "=r"(a) : "l"(p));
    return a;
}
__device__ __forceinline__ uint32_t bf16pair(float lo, float hi) {
    uint32_t r;
    asm("cvt.rn.bf16x2.f32 %0, %1, %2;" : "=r"(r) : "f"(hi), "f"(lo));
    return r;
}
__device__ __forceinline__ void ldmx4(uint32_t* r, uint32_t a) {
    asm volatile("ldmatrix.sync.aligned.m8n8.x4.shared.b16 {%0,%1,%2,%3}, [%4];"
        : "=r"(r[0]), "=r"(r[1]), "=r"(r[2]), "=r"(r[3]) : "r"(a));
}
__device__ __forceinline__ void mma16816(float* d, const uint32_t* a, const uint32_t* b) {
    asm volatile("mma.sync.aligned.m16n8k16.row.col.f32.bf16.bf16.f32 "
        "{%0,%1,%2,%3}, {%4,%5,%6,%7}, {%8,%9}, {%0,%1,%2,%3};"
        : "+f"(d[0]), "+f"(d[1]), "+f"(d[2]), "+f"(d[3])
        : "r"(a[0]), "r"(a[1]), "r"(a[2]), "r"(a[3]), "r"(b[0]), "r"(b[1]));
}
__inline__ __device__ float warpReduceSum(float v) {
    #pragma unroll
    for (int o = 16; o > 0; o >>= 1) v += __shfl_down_sync(0xffffffffu, v, o);
    return v;
}
// EXACT frozen distance: a0..a3 over j%4, (a0+a1)+(a2+a3), (sx+sc)-2dot
__device__ __forceinline__ float exact_d(const float* __restrict__ crow,
                                         const float* __restrict__ xrow,
                                         float sx, float sck) {
    float a0 = 0.f, a1 = 0.f, a2 = 0.f, a3 = 0.f;
    #pragma unroll
    for (int j = 0; j < DCH; j += 4) {
        float4 c  = *(const float4*)(crow + j);
        float4 xx = *(const float4*)(xrow + j);
        a0 = fmaf(c.x, xx.x, a0);
        a1 = fmaf(c.y, xx.y, a1);
        a2 = fmaf(c.z, xx.z, a2);
        a3 = fmaf(c.w, xx.w, a3);
    }
    return (sx + sck) - 2.0f * ((a0 + a1) + (a2 + a3));
}
// best-3 insert: values m1<=m2<=m3, indices for m1,m2 only
__device__ __forceinline__ void ins3(float e, int k, float& m1, float& m2,
                                     float& m3, int& k1, int& k2) {
    if (e < m1)      { m3 = m2; m2 = m1; k2 = k1; m1 = e; k1 = k; }
    else if (e < m2) { m3 = m2; m2 = e; k2 = k; }
    else if (e < m3) { m3 = e; }
}

__global__ __launch_bounds__(BLOCK_MAIN, 2)
void vq_hmma(const float* __restrict__ in, const float* __restrict__ cb,
             float* __restrict__ out) {
    extern __shared__ char smem[];
    uint32_t sbase = smem_u32(smem);
    float* XF    = (float*)(smem + SM_XF);
    float* ssc   = (float*)(smem + SM_SSC);
    float* sxs   = (float*)(smem + SM_SXS);
    int*   sbidx = (int*)  (smem + SM_BIDX);
    float* sloss = (float*)(smem + SM_LOSS);

    int tid = threadIdx.x, lane = tid & 31, w = tid >> 5;
    int dv = tid & 63, h = tid >> 6;
    int qr = lane >> 2, qc2 = (lane & 3) * 2;

    // ---- codebook bf16 -> SMEM B; exact fp32 norms (reference order) ----
    const float4* cb4 = (const float4*)cb;
    for (int i = tid; i < KCODES * 16; i += BLOCK_MAIN) {
        int k = i >> 4, j4 = i & 15;
        float4 v = cb4[i];
        char* dst = smem + SM_B + k * B_STRIDE + j4 * 8;
        *(uint32_t*)(dst)     = bf16pair(v.x, v.y);
        *(uint32_t*)(dst + 4) = bf16pair(v.z, v.w);
    }
    for (int k = tid; k < KCODES; k += BLOCK_MAIN) {
        const float* c = cb + (size_t)k * DCH;
        float s = 0.f;
        #pragma unroll
        for (int j = 0; j < DCH; j++) s = fmaf(c[j], c[j], s);
        ssc[k] = s;
    }
    __syncthreads();

    float threadLoss = 0.f;

    for (int tile = blockIdx.x; tile < NTILES; tile += GRID_MAIN) {
        int v0 = tile * TILE_M;
        int b  = v0 >> 15;
        int s0 = v0 & (SPATIAL - 1);
        const float* xbase = in + (size_t)b * DCH * SPATIAL + s0 + dv;

        // ---- fill A (bf16) + XF (fp32) ----
        #pragma unroll
        for (int jj = 0; jj < 32; jj += 2) {
            int j = h * 32 + jj;
            float x0 = xbase[(size_t)j * SPATIAL];
            float x1 = xbase[(size_t)(j + 1) * SPATIAL];
            *(uint32_t*)(smem + SM_A + dv * A_STRIDE + j * 2) = bf16pair(x0, x1);
            *(float2*)(XF + dv * XF_STRIDE + j) = make_float2(x0, x1);
        }
        __syncthreads();

        if (tid < TILE_M) {   // frozen sequential sx
            const float* xr = XF + tid * XF_STRIDE;
            float s = 0.f;
            #pragma unroll
            for (int j = 0; j < DCH; j++) s = fmaf(xr[j], xr[j], s);
            sxs[tid] = s;
        }

        // ---- A fragments ----
        uint32_t afr[4][4];
        int g = lane >> 3, r = lane & 7;
        #pragma unroll
        for (int kc = 0; kc < 4; kc++) {
            uint32_t aaddr = sbase + SM_A
                + (uint32_t)((w * 16 + r + (g & 1) * 8) * A_STRIDE)
                + (uint32_t)((kc * 16 + (g >> 1) * 8) * 2);
            ldmx4(afr[kc], aaddr);
        }
        uint32_t bbase = sbase + SM_B
            + (uint32_t)(((g >> 1) * 8 + r) * B_STRIDE)
            + (uint32_t)((g & 1) * 16);

        // ---- single pass: scores + per-thread best-3 (2 rows) ----
        float m10 = FLT_MAX, m20 = FLT_MAX, m30 = FLT_MAX;
        float m18 = FLT_MAX, m28 = FLT_MAX, m38 = FLT_MAX;
        int k10 = KCODES, k20 = KCODES, k18 = KCODES, k28 = KCODES;

        for (int nt = 0; nt < 64; nt += 2) {
            float d0[4] = {0.f, 0.f, 0.f, 0.f};
            float d1[4] = {0.f, 0.f, 0.f, 0.f};
            uint32_t brow = bbase + (uint32_t)(nt * 8 * B_STRIDE);
            #pragma unroll
            for (int kc = 0; kc < 4; kc++) {
                uint32_t bf[4];
                ldmx4(bf, brow + kc * 32);
                mma16816(d0, afr[kc], bf + 0);
                mma16816(d1, afr[kc], bf + 2);
            }
            float2 sA = *(const float2*)(ssc + nt * 8 + qc2);
            float2 sB = *(const float2*)(ssc + nt * 8 + 8 + qc2);
            int kA = nt * 8 + qc2, kB = nt * 8 + 8 + qc2;
            // row r0 scores
            float e00 = sA.x - 2.f * d0[0], e01 = sA.y - 2.f * d0[1];
            float e02 = sB.x - 2.f * d1[0], e03 = sB.y - 2.f * d1[1];
            float l0 = fminf(fminf(e00, e01), fminf(e02, e03));
            if (l0 < m30) {   // group can touch best-3 only if local min beats m3
                ins3(e00, kA,     m10, m20, m30, k10, k20);
                ins3(e01, kA + 1, m10, m20, m30, k10, k20);
                ins3(e02, kB,     m10, m20, m30, k10, k20);
                ins3(e03, kB + 1, m10, m20, m30, k10, k20);
            }
            // row r8 scores
            float e10 = sA.x - 2.f * d0[2], e11 = sA.y - 2.f * d0[3];
            float e12 = sB.x - 2.f * d1[2], e13 = sB.y - 2.f * d1[3];
            float l1 = fminf(fminf(e10, e11), fminf(e12, e13));
            if (l1 < m38) {
                ins3(e10, kA,     m18, m28, m38, k18, k28);
                ins3(e11, kA + 1, m18, m28, m38, k18, k28);
                ins3(e12, kB,     m18, m28, m38, k18, k28);
                ins3(e13, kB + 1, m18, m28, m38, k18, k28);
            }
        }
        // quad-reduce global approx min per row
        float gm0 = m10, gm8 = m18;
        #pragma unroll
        for (int o = 1; o < 4; o <<= 1) {
            gm0 = fminf(gm0, __shfl_xor_sync(0xffffffffu, gm0, o));
            gm8 = fminf(gm8, __shfl_xor_sync(0xffffffffu, gm8, o));
        }
        float thr0 = gm0 + MARGIN, thr8 = gm8 + MARGIN;
        __syncthreads();   // sxs visible

        // ---- exact recheck of candidates ----
        int r0 = w * 16 + qr, r8 = r0 + 8;
        const float* x0row = XF + r0 * XF_STRIDE;
        const float* x8row = XF + r8 * XF_STRIDE;
        float sx0 = sxs[r0], sx8 = sxs[r8];

        float bd0 = FLT_MAX, bd8 = FLT_MAX;
        int   bi0 = KCODES,  bi8 = KCODES;

        if (m30 <= thr0) {   // rare: >=3 within margin in this thread -> exact scan own 128 k's
            for (int nt = 0; nt < 64; nt++) {
                int k = nt * 8 + qc2;
                float d = exact_d(cb + (size_t)k * DCH, x0row, sx0, ssc[k]);
                if (d < bd0) { bd0 = d; bi0 = k; }
                d = exact_d(cb + (size_t)(k + 1) * DCH, x0row, sx0, ssc[k + 1]);
                if (d < bd0) { bd0 = d; bi0 = k + 1; }
            }
        } else {
            if (m10 <= thr0) {
                float d = exact_d(cb + (size_t)k10 * DCH, x0row, sx0, ssc[k10]);
                if (d < bd0 || (d == bd0 && k10 < bi0)) { bd0 = d; bi0 = k10; }
            }
            if (m20 <= thr0) {
                float d = exact_d(cb + (size_t)k20 * DCH, x0row, sx0, ssc[k20]);
                if (d < bd0 || (d == bd0 && k20 < bi0)) { bd0 = d; bi0 = k20; }
            }
        }
        if (m38 <= thr8) {
            for (int nt = 0; nt < 64; nt++) {
                int k = nt * 8 + qc2;
                float d = exact_d(cb + (size_t)k * DCH, x8row, sx8, ssc[k]);
                if (d < bd8) { bd8 = d; bi8 = k; }
                d = exact_d(cb + (size_t)(k + 1) * DCH, x8row, sx8, ssc[k + 1]);
                if (d < bd8) { bd8 = d; bi8 = k + 1; }
            }
        } else {
            if (m18 <= thr8) {
                float d = exact_d(cb + (size_t)k18 * DCH, x8row, sx8, ssc[k18]);
                if (d < bd8 || (d == bd8 && k18 < bi8)) { bd8 = d; bi8 = k18; }
            }
            if (m28 <= thr8) {
                float d = exact_d(cb + (size_t)k28 * DCH, x8row, sx8, ssc[k28]);
                if (d < bd8 || (d == bd8 && k28 < bi8)) { bd8 = d; bi8 = k28; }
            }
        }
        // quad combine with first-min (smallest-k) tie-break
        #pragma unroll
        for (int o = 1; o < 4; o <<= 1) {
            float od = __shfl_xor_sync(0xffffffffu, bd0, o);
            int   oi = __shfl_xor_sync(0xffffffffu, bi0, o);
            if (od < bd0 || (od == bd0 && oi < bi0)) { bd0 = od; bi0 = oi; }
            od = __shfl_xor_sync(0xffffffffu, bd8, o);
            oi = __shfl_xor_sync(0xffffffffu, bi8, o);
            if (od < bd8 || (od == bd8 && oi < bi8)) { bd8 = od; bi8 = oi; }
        }
        if ((lane & 3) == 0) {
            sbidx[r0] = bi0;
            sbidx[r8] = bi8;
            out[IDX_OFF + v0 + r0] = (float)bi0;
            out[IDX_OFF + v0 + r8] = (float)bi8;
        }
        __syncthreads();

        // ---- epilogue: STE store x + (c - x); cb rows via float4 ----
        {
            int bidx = sbidx[dv];
            const float* crow = cb + (size_t)bidx * DCH + h * 32;
            const float* xr   = XF + dv * XF_STRIDE + h * 32;
            float* qout = out + (size_t)b * DCH * SPATIAL + s0 + dv
                        + (size_t)h * 32 * SPATIAL;
            #pragma unroll
            for (int q4 = 0; q4 < 8; q4++) {
                float4 c  = *(const float4*)(crow + q4 * 4);
                float4 xv = *(const float4*)(xr + q4 * 4);
                float dd;
                dd = c.x - xv.x; qout[(size_t)(q4 * 4 + 0) * SPATIAL] = xv.x + dd;
                threadLoss = fmaf(dd, dd, threadLoss);
                dd = c.y - xv.y; qout[(size_t)(q4 * 4 + 1) * SPATIAL] = xv.y + dd;
                threadLoss = fmaf(dd, dd, threadLoss);
                dd = c.z - xv.z; qout[(size_t)(q4 * 4 + 2) * SPATIAL] = xv.z + dd;
                threadLoss = fmaf(dd, dd, threadLoss);
                dd = c.w - xv.w; qout[(size_t)(q4 * 4 + 3) * SPATIAL] = xv.w + dd;
                threadLoss = fmaf(dd, dd, threadLoss);
            }
        }
        __syncthreads();
    }

    // ---- loss reduction ----
    float ws = warpReduceSum(threadLoss);
    if (lane == 0) sloss[w] = ws;
    __syncthreads();
    if (tid == 0) {
        double t = 0.0;
        for (int i = 0; i < 4; i++) t += (double)sloss[i];
        g_blocksums[blockIdx.x] = t;
    }
}

__global__ void vq_finalize(float* __restrict__ out) {
    if (threadIdx.x == 0 && blockIdx.x == 0) {
        double t = 0.0;
        for (int i = 0; i < GRID_MAIN; i++) t += g_blocksums[i];
        out[LOSS_OFF] = (float)(1.25 * t / (double)Q_ELEMS);
    }
}

__global__ void vq_nop() {}

extern "C" void kernel_launch(void* const* d_in, const int* in_sizes, int n_in,
                              void* d_out, int out_size) {
    const float* in = (const float*)d_in[0];
    const float* cb = (const float*)d_in[1];
    float* out = (float*)d_out;

    static bool attr_set = false;
    if (!attr_set) {
        cudaFuncSetAttribute(vq_hmma, cudaFuncAttributeMaxDynamicSharedMemorySize, SM_TOTAL);
        attr_set = true;
    }

    vq_nop<<<1, 32>>>();
    vq_nop<<<1, 32>>>();
    vq_nop<<<1, 32>>>();
    vq_hmma<<<GRID_MAIN, BLOCK_MAIN, SM_TOTAL>>>(in, cb, out);
    vq_finalize<<<1, 32>>>(out);
}

// round 14
// speedup vs baseline: 3.2350x; 3.2350x over previous
#include <cuda_runtime.h>
#include <cstdint>
#include <cfloat>

// VectorQuantizer on B200 — round 14: round-13 (TILE_M=128, two-pass HMMA,
// x re-read from global) with the dead-line compile error removed.
#define KCODES    512
#define DCH       64
#define SPATIAL   32768
#define NVEC      262144
#define Q_ELEMS   16777216
#define LOSS_OFF  Q_ELEMS
#define IDX_OFF   (Q_ELEMS + 1)
#define TILE_M    128
#define NTILES    (NVEC / TILE_M)   // 2048
#define GRID_MAIN 296               // 2 CTAs per SM
#define BLOCK_MAIN 128
#define MARGIN    3e-3f
#define MAXC      6

#define A_STRIDE   144
#define B_STRIDE   144
#define SM_A       0                // 128*144 = 18432
#define SM_B       18432            // 512*144 = 73728
#define SM_SSC     92160            // 2048
#define SM_BIDX    94208            // 512
#define SM_LOSS    94720            // 16
#define SM_TOTAL   94736

__device__ double g_blocksums[GRID_MAIN];

__device__ __forceinline__ uint32_t smem_u32(const void* p) {
    uint32_t a;
    asm("{ .reg .u64 t; cvta.to.shared.u64 t, %1; cvt.u32.u64 %0, t; }" : "=r"(a) : "l"(p));
    return a;
}
__device__ __forceinline__ uint32_t bf16pair(float lo, float hi) {
    uint32_t r;
    asm("cvt.rn.bf16x2.f32 %0, %1, %2;" : "=r"(r) : "f"(hi), "f"(lo));
    return r;
}
__device__ __forceinline__ void ldmx4(uint32_t* r, uint32_t a) {
    asm volatile("ldmatrix.sync.aligned.m8n8.x4.shared.b16 {%0,%1,%2,%3}, [%4];"
        : "=r"(r[0]), "=r"(r[1]), "=r"(r[2]), "=r"(r[3]) : "r"(a));
}
__device__ __forceinline__ void mma16816(float* d, const uint32_t* a, const uint32_t* b) {
    asm volatile("mma.sync.aligned.m16n8k16.row.col.f32.bf16.bf16.f32 "
        "{%0,%1,%2,%3}, {%4,%5,%6,%7}, {%8,%9}, {%0,%1,%2,%3};"
        : "+f"(d[0]), "+f"(d[1]), "+f"(d[2]), "+f"(d[3])
        : "r"(a[0]), "r"(a[1]), "r"(a[2]), "r"(a[3]), "r"(b[0]), "r"(b[1]));
}
__inline__ __device__ float warpReduceSum(float v) {
    #pragma unroll
    for (int o = 16; o > 0; o >>= 1) v += __shfl_down_sync(0xffffffffu, v, o);
    return v;
}
// EXACT frozen distance: a0..a3 over j%4, (a0+a1)+(a2+a3), (sx+sc)-2dot
__device__ __forceinline__ float exact_d(const float* __restrict__ crow,
                                         const float (&x)[DCH], float sx, float sck) {
    float a0 = 0.f, a1 = 0.f, a2 = 0.f, a3 = 0.f;
    #pragma unroll
    for (int j = 0; j < DCH; j += 4) {
        float4 c = *(const float4*)(crow + j);
        a0 = fmaf(c.x, x[j + 0], a0);
        a1 = fmaf(c.y, x[j + 1], a1);
        a2 = fmaf(c.z, x[j + 2], a2);
        a3 = fmaf(c.w, x[j + 3], a3);
    }
    return (sx + sck) - 2.0f * ((a0 + a1) + (a2 + a3));
}

__global__ __launch_bounds__(BLOCK_MAIN, 2)
void vq_hmma(const float* __restrict__ in, const float* __restrict__ cb,
             float* __restrict__ out) {
    extern __shared__ char smem[];
    uint32_t sbase = smem_u32(smem);
    float* ssc   = (float*)(smem + SM_SSC);
    int*   sbidx = (int*)  (smem + SM_BIDX);
    float* sloss = (float*)(smem + SM_LOSS);

    int tid = threadIdx.x, lane = tid & 31, w = tid >> 5;
    int qr = lane >> 2, qc2 = (lane & 3) * 2;

    // ---- codebook bf16 -> SMEM B; exact fp32 norms (reference order) ----
    const float4* cb4 = (const float4*)cb;
    for (int i = tid; i < KCODES * 16; i += BLOCK_MAIN) {
        int k = i >> 4, j4 = i & 15;
        float4 v = cb4[i];
        char* dst = smem + SM_B + k * B_STRIDE + j4 * 8;
        *(uint32_t*)(dst)     = bf16pair(v.x, v.y);
        *(uint32_t*)(dst + 4) = bf16pair(v.z, v.w);
    }
    for (int k = tid; k < KCODES; k += BLOCK_MAIN) {
        const float* c = cb + (size_t)k * DCH;
        float s = 0.f;
        #pragma unroll
        for (int j = 0; j < DCH; j++) s = fmaf(c[j], c[j], s);
        ssc[k] = s;
    }
    __syncthreads();

    float threadLoss = 0.f;

    for (int tile = blockIdx.x; tile < NTILES; tile += GRID_MAIN) {
        int v0 = tile * TILE_M;
        int b  = v0 >> 15;
        int s0 = v0 & (SPATIAL - 1);

        // ---- A fill: thread tid owns row tid (all 64 channels) ----
        {
            const float* xg = in + (size_t)b * DCH * SPATIAL + s0 + tid;
            #pragma unroll
            for (int j = 0; j < DCH; j += 2) {
                float x0 = xg[(size_t)j * SPATIAL];
                float x1 = xg[(size_t)(j + 1) * SPATIAL];
                *(uint32_t*)(smem + SM_A + tid * A_STRIDE + j * 2) = bf16pair(x0, x1);
            }
        }
        __syncthreads();

        // ---- A fragments: 2 m16 blocks per warp (rows 32w..32w+31) ----
        uint32_t afr[2][4][4];
        int g = lane >> 3, r = lane & 7;
        #pragma unroll
        for (int bi = 0; bi < 2; bi++)
            #pragma unroll
            for (int kc = 0; kc < 4; kc++) {
                uint32_t aaddr = sbase + SM_A
                    + (uint32_t)((w * 32 + bi * 16 + r + (g & 1) * 8) * A_STRIDE)
                    + (uint32_t)((kc * 16 + (g >> 1) * 8) * 2);
                ldmx4(afr[bi][kc], aaddr);
            }
        uint32_t bbase = sbase + SM_B
            + (uint32_t)(((g >> 1) * 8 + r) * B_STRIDE)
            + (uint32_t)((g & 1) * 16);

        // ---- pass 1: running mins for this thread's 4 rows ----
        // row order: [0]=32w+qr [1]=32w+qr+8 [2]=32w+16+qr [3]=32w+24+qr
        float mrow[4] = {FLT_MAX, FLT_MAX, FLT_MAX, FLT_MAX};
        for (int nt = 0; nt < 64; nt += 2) {
            float dA0[4] = {0.f,0.f,0.f,0.f}, dA1[4] = {0.f,0.f,0.f,0.f};
            float dB0[4] = {0.f,0.f,0.f,0.f}, dB1[4] = {0.f,0.f,0.f,0.f};
            uint32_t brow = bbase + (uint32_t)(nt * 8 * B_STRIDE);
            #pragma unroll
            for (int kc = 0; kc < 4; kc++) {
                uint32_t bf[4];
                ldmx4(bf, brow + kc * 32);
                mma16816(dA0, afr[0][kc], bf + 0);
                mma16816(dA1, afr[0][kc], bf + 2);
                mma16816(dB0, afr[1][kc], bf + 0);
                mma16816(dB1, afr[1][kc], bf + 2);
            }
            float2 sA = *(const float2*)(ssc + nt * 8 + qc2);
            float2 sB = *(const float2*)(ssc + nt * 8 + 8 + qc2);
            mrow[0] = fminf(mrow[0], fminf(fminf(sA.x - 2.f*dA0[0], sA.y - 2.f*dA0[1]),
                                           fminf(sB.x - 2.f*dA1[0], sB.y - 2.f*dA1[1])));
            mrow[1] = fminf(mrow[1], fminf(fminf(sA.x - 2.f*dA0[2], sA.y - 2.f*dA0[3]),
                                           fminf(sB.x - 2.f*dA1[2], sB.y - 2.f*dA1[3])));
            mrow[2] = fminf(mrow[2], fminf(fminf(sA.x - 2.f*dB0[0], sA.y - 2.f*dB0[1]),
                                           fminf(sB.x - 2.f*dB1[0], sB.y - 2.f*dB1[1])));
            mrow[3] = fminf(mrow[3], fminf(fminf(sA.x - 2.f*dB0[2], sA.y - 2.f*dB0[3]),
                                           fminf(sB.x - 2.f*dB1[2], sB.y - 2.f*dB1[3])));
        }
        float thr[4];
        #pragma unroll
        for (int i = 0; i < 4; i++) {
            float m = mrow[i];
            #pragma unroll
            for (int o = 1; o < 4; o <<= 1)
                m = fminf(m, __shfl_xor_sync(0xffffffffu, m, o));
            thr[i] = m + MARGIN;
        }

        // ---- pass 2: recompute, collect candidates per row ----
        int cand[4][MAXC];
        int nc[4] = {0, 0, 0, 0};
        bool ov[4] = {false, false, false, false};
        for (int nt = 0; nt < 64; nt += 2) {
            float dA0[4] = {0.f,0.f,0.f,0.f}, dA1[4] = {0.f,0.f,0.f,0.f};
            float dB0[4] = {0.f,0.f,0.f,0.f}, dB1[4] = {0.f,0.f,0.f,0.f};
            uint32_t brow = bbase + (uint32_t)(nt * 8 * B_STRIDE);
            #pragma unroll
            for (int kc = 0; kc < 4; kc++) {
                uint32_t bf[4];
                ldmx4(bf, brow + kc * 32);
                mma16816(dA0, afr[0][kc], bf + 0);
                mma16816(dA1, afr[0][kc], bf + 2);
                mma16816(dB0, afr[1][kc], bf + 0);
                mma16816(dB1, afr[1][kc], bf + 2);
            }
            float2 sA = *(const float2*)(ssc + nt * 8 + qc2);
            float2 sB = *(const float2*)(ssc + nt * 8 + 8 + qc2);
            int kA = nt * 8 + qc2, kB = nt * 8 + 8 + qc2;
            #pragma unroll
            for (int i = 0; i < 4; i++) {
                float e0, e1, e2, e3;
                if (i == 0) { e0 = sA.x-2.f*dA0[0]; e1 = sA.y-2.f*dA0[1]; e2 = sB.x-2.f*dA1[0]; e3 = sB.y-2.f*dA1[1]; }
                else if (i == 1) { e0 = sA.x-2.f*dA0[2]; e1 = sA.y-2.f*dA0[3]; e2 = sB.x-2.f*dA1[2]; e3 = sB.y-2.f*dA1[3]; }
                else if (i == 2) { e0 = sA.x-2.f*dB0[0]; e1 = sA.y-2.f*dB0[1]; e2 = sB.x-2.f*dB1[0]; e3 = sB.y-2.f*dB1[1]; }
                else             { e0 = sA.x-2.f*dB0[2]; e1 = sA.y-2.f*dB0[3]; e2 = sB.x-2.f*dB1[2]; e3 = sB.y-2.f*dB1[3]; }
                if (e0 <= thr[i]) { if (nc[i] < MAXC) cand[i][nc[i]++] = kA;     else ov[i] = true; }
                if (e1 <= thr[i]) { if (nc[i] < MAXC) cand[i][nc[i]++] = kA + 1; else ov[i] = true; }
                if (e2 <= thr[i]) { if (nc[i] < MAXC) cand[i][nc[i]++] = kB;     else ov[i] = true; }
                if (e3 <= thr[i]) { if (nc[i] < MAXC) cand[i][nc[i]++] = kB + 1; else ov[i] = true; }
            }
        }

        // ---- exact recheck per row; x re-read from global (round-9 style) ----
        #pragma unroll
        for (int i = 0; i < 4; i++) {
            int row = w * 32 + (i >> 1) * 16 + (i & 1) * 8 + qr;
            float bd = FLT_MAX;
            int   bi = KCODES;
            if (nc[i] > 0 || ov[i]) {
                const float* xg = in + (size_t)b * DCH * SPATIAL + s0 + row;
                float x[DCH];
                #pragma unroll
                for (int j = 0; j < DCH; j++) x[j] = xg[(size_t)j * SPATIAL];
                float sx = 0.f;                       // frozen sequential order
                #pragma unroll
                for (int j = 0; j < DCH; j++) sx = fmaf(x[j], x[j], sx);
                if (!ov[i]) {
                    for (int ci = 0; ci < nc[i]; ci++) {
                        int k = cand[i][ci];
                        float d = exact_d(cb + (size_t)k * DCH, x, sx, ssc[k]);
                        if (d < bd || (d == bd && k < bi)) { bd = d; bi = k; }
                    }
                } else {   // rare: exact scan of this thread's own 128 k's
                    for (int nt = 0; nt < 64; nt++) {
                        int k = nt * 8 + qc2;
                        float d = exact_d(cb + (size_t)k * DCH, x, sx, ssc[k]);
                        if (d < bd) { bd = d; bi = k; }
                        d = exact_d(cb + (size_t)(k + 1) * DCH, x, sx, ssc[k + 1]);
                        if (d < bd) { bd = d; bi = k + 1; }
                    }
                }
            }
            // quad combine with first-min (smallest-k) tie-break
            #pragma unroll
            for (int o = 1; o < 4; o <<= 1) {
                float od = __shfl_xor_sync(0xffffffffu, bd, o);
                int   oi = __shfl_xor_sync(0xffffffffu, bi, o);
                if (od < bd || (od == bd && oi < bi)) { bd = od; bi = oi; }
            }
            if ((lane & 3) == 0) {
                sbidx[row] = bi;
                out[IDX_OFF + v0 + row] = (float)bi;
            }
        }
        __syncthreads();

        // ---- epilogue: thread tid owns row tid; STE store x + (c - x) ----
        {
            int bidx = sbidx[tid];
            const float* crow = cb + (size_t)bidx * DCH;
            const float* xg = in + (size_t)b * DCH * SPATIAL + s0 + tid;
            float* qout = out + (size_t)b * DCH * SPATIAL + s0 + tid;
            #pragma unroll
            for (int j4 = 0; j4 < DCH; j4 += 4) {
                float4 c = *(const float4*)(crow + j4);
                float xv, dd;
                xv = xg[(size_t)(j4 + 0) * SPATIAL]; dd = c.x - xv;
                qout[(size_t)(j4 + 0) * SPATIAL] = xv + dd; threadLoss = fmaf(dd, dd, threadLoss);
                xv = xg[(size_t)(j4 + 1) * SPATIAL]; dd = c.y - xv;
                qout[(size_t)(j4 + 1) * SPATIAL] = xv + dd; threadLoss = fmaf(dd, dd, threadLoss);
                xv = xg[(size_t)(j4 + 2) * SPATIAL]; dd = c.z - xv;
                qout[(size_t)(j4 + 2) * SPATIAL] = xv + dd; threadLoss = fmaf(dd, dd, threadLoss);
                xv = xg[(size_t)(j4 + 3) * SPATIAL]; dd = c.w - xv;
                qout[(size_t)(j4 + 3) * SPATIAL] = xv + dd; threadLoss = fmaf(dd, dd, threadLoss);
            }
        }
        __syncthreads();   // protect A before next fill
    }

    // ---- loss reduction ----
    float ws = warpReduceSum(threadLoss);
    if (lane == 0) sloss[w] = ws;
    __syncthreads();
    if (tid == 0) {
        double t = 0.0;
        for (int i = 0; i < 4; i++) t += (double)sloss[i];
        g_blocksums[blockIdx.x] = t;
    }
}

__global__ void vq_finalize(float* __restrict__ out) {
    if (threadIdx.x == 0 && blockIdx.x == 0) {
        double t = 0.0;
        for (int i = 0; i < GRID_MAIN; i++) t += g_blocksums[i];
        out[LOSS_OFF] = (float)(1.25 * t / (double)Q_ELEMS);
    }
}

__global__ void vq_nop() {}

extern "C" void kernel_launch(void* const* d_in, const int* in_sizes, int n_in,
                              void* d_out, int out_size) {
    const float* in = (const float*)d_in[0];
    const float* cb = (const float*)d_in[1];
    float* out = (float*)d_out;

    static bool attr_set = false;
    if (!attr_set) {
        cudaFuncSetAttribute(vq_hmma, cudaFuncAttributeMaxDynamicSharedMemorySize, SM_TOTAL);
        attr_set = true;
    }

    vq_nop<<<1, 32>>>();
    vq_nop<<<1, 32>>>();
    vq_nop<<<1, 32>>>();
    vq_hmma<<<GRID_MAIN, BLOCK_MAIN, SM_TOTAL>>>(in, cb, out);
    vq_finalize<<<1, 32>>>(out);
}

// round 15
// speedup vs baseline: 3.8408x; 1.1873x over previous
#include <cuda_runtime.h>
#include <cstdint>
#include <cfloat>

// VectorQuantizer on B200 — round 15: BLOCK=256 (8 warps, 1 m16-block each),
// TILE_M=128, 2 CTAs/SM -> 16 warps/SM for latency hiding. Numerics identical
// to rounds 11/14 (bit-exact indices).
#define KCODES    512
#define DCH       64
#define SPATIAL   32768
#define NVEC      262144
#define Q_ELEMS   16777216
#define LOSS_OFF  Q_ELEMS
#define IDX_OFF   (Q_ELEMS + 1)
#define TILE_M    128
#define NTILES    (NVEC / TILE_M)   // 2048
#define GRID_MAIN 296               // 2 CTAs per SM
#define BLOCK_MAIN 256
#define MARGIN    3e-3f
#define MAXC      6

#define A_STRIDE   144
#define B_STRIDE   144
#define SM_A       0                // 128*144 = 18432
#define SM_B       18432            // 512*144 = 73728
#define SM_SSC     92160            // 2048
#define SM_BIDX    94208            // 512
#define SM_LOSS    94720            // 32
#define SM_TOTAL   94752

__device__ double g_blocksums[GRID_MAIN];

__device__ __forceinline__ uint32_t smem_u32(const void* p) {
    uint32_t a;
    asm("{ .reg .u64 t; cvta.to.shared.u64 t, %1; cvt.u32.u64 %0, t; }" : "=r"(a) : "l"(p));
    return a;
}
__device__ __forceinline__ uint32_t bf16pair(float lo, float hi) {
    uint32_t r;
    asm("cvt.rn.bf16x2.f32 %0, %1, %2;" : "=r"(r) : "f"(hi), "f"(lo));
    return r;
}
__device__ __forceinline__ void ldmx4(uint32_t* r, uint32_t a) {
    asm volatile("ldmatrix.sync.aligned.m8n8.x4.shared.b16 {%0,%1,%2,%3}, [%4];"
        : "=r"(r[0]), "=r"(r[1]), "=r"(r[2]), "=r"(r[3]) : "r"(a));
}
__device__ __forceinline__ void mma16816(float* d, const uint32_t* a, const uint32_t* b) {
    asm volatile("mma.sync.aligned.m16n8k16.row.col.f32.bf16.bf16.f32 "
        "{%0,%1,%2,%3}, {%4,%5,%6,%7}, {%8,%9}, {%0,%1,%2,%3};"
        : "+f"(d[0]), "+f"(d[1]), "+f"(d[2]), "+f"(d[3])
        : "r"(a[0]), "r"(a[1]), "r"(a[2]), "r"(a[3]), "r"(b[0]), "r"(b[1]));
}
__inline__ __device__ float warpReduceSum(float v) {
    #pragma unroll
    for (int o = 16; o > 0; o >>= 1) v += __shfl_down_sync(0xffffffffu, v, o);
    return v;
}
// EXACT frozen distance: a0..a3 over j%4, (a0+a1)+(a2+a3), (sx+sc)-2dot
__device__ __forceinline__ float exact_d(const float* __restrict__ crow,
                                         const float (&x)[DCH], float sx, float sck) {
    float a0 = 0.f, a1 = 0.f, a2 = 0.f, a3 = 0.f;
    #pragma unroll
    for (int j = 0; j < DCH; j += 4) {
        float4 c = *(const float4*)(crow + j);
        a0 = fmaf(c.x, x[j + 0], a0);
        a1 = fmaf(c.y, x[j + 1], a1);
        a2 = fmaf(c.z, x[j + 2], a2);
        a3 = fmaf(c.w, x[j + 3], a3);
    }
    return (sx + sck) - 2.0f * ((a0 + a1) + (a2 + a3));
}

__global__ __launch_bounds__(BLOCK_MAIN, 2)
void vq_hmma(const float* __restrict__ in, const float* __restrict__ cb,
             float* __restrict__ out) {
    extern __shared__ char smem[];
    uint32_t sbase = smem_u32(smem);
    float* ssc   = (float*)(smem + SM_SSC);
    int*   sbidx = (int*)  (smem + SM_BIDX);
    float* sloss = (float*)(smem + SM_LOSS);

    int tid = threadIdx.x, lane = tid & 31, w = tid >> 5;   // w in 0..7
    int dv = tid & 127, h = tid >> 7;                        // fill/epilogue row+half
    int qr = lane >> 2, qc2 = (lane & 3) * 2;

    // ---- codebook bf16 -> SMEM B; exact fp32 norms (reference order) ----
    const float4* cb4 = (const float4*)cb;
    for (int i = tid; i < KCODES * 16; i += BLOCK_MAIN) {
        int k = i >> 4, j4 = i & 15;
        float4 v = cb4[i];
        char* dst = smem + SM_B + k * B_STRIDE + j4 * 8;
        *(uint32_t*)(dst)     = bf16pair(v.x, v.y);
        *(uint32_t*)(dst + 4) = bf16pair(v.z, v.w);
    }
    for (int k = tid; k < KCODES; k += BLOCK_MAIN) {
        const float* c = cb + (size_t)k * DCH;
        float s = 0.f;
        #pragma unroll
        for (int j = 0; j < DCH; j++) s = fmaf(c[j], c[j], s);
        ssc[k] = s;
    }
    __syncthreads();

    float threadLoss = 0.f;

    for (int tile = blockIdx.x; tile < NTILES; tile += GRID_MAIN) {
        int v0 = tile * TILE_M;
        int b  = v0 >> 15;
        int s0 = v0 & (SPATIAL - 1);

        // ---- A fill: thread -> row dv, channel half h ----
        {
            const float* xg = in + (size_t)b * DCH * SPATIAL + s0 + dv;
            #pragma unroll
            for (int jj = 0; jj < 32; jj += 2) {
                int j = h * 32 + jj;
                float x0 = xg[(size_t)j * SPATIAL];
                float x1 = xg[(size_t)(j + 1) * SPATIAL];
                *(uint32_t*)(smem + SM_A + dv * A_STRIDE + j * 2) = bf16pair(x0, x1);
            }
        }
        __syncthreads();

        // ---- A fragments: warp w -> rows 16w..16w+15 ----
        uint32_t afr[4][4];
        int g = lane >> 3, r = lane & 7;
        #pragma unroll
        for (int kc = 0; kc < 4; kc++) {
            uint32_t aaddr = sbase + SM_A
                + (uint32_t)((w * 16 + r + (g & 1) * 8) * A_STRIDE)
                + (uint32_t)((kc * 16 + (g >> 1) * 8) * 2);
            ldmx4(afr[kc], aaddr);
        }
        uint32_t bbase = sbase + SM_B
            + (uint32_t)(((g >> 1) * 8 + r) * B_STRIDE)
            + (uint32_t)((g & 1) * 16);

        // ---- pass 1: running min for this thread's 2 rows ----
        float m0 = FLT_MAX, m8 = FLT_MAX;
        for (int nt = 0; nt < 64; nt += 2) {
            float d0[4] = {0.f, 0.f, 0.f, 0.f};
            float d1[4] = {0.f, 0.f, 0.f, 0.f};
            uint32_t brow = bbase + (uint32_t)(nt * 8 * B_STRIDE);
            #pragma unroll
            for (int kc = 0; kc < 4; kc++) {
                uint32_t bf[4];
                ldmx4(bf, brow + kc * 32);
                mma16816(d0, afr[kc], bf + 0);
                mma16816(d1, afr[kc], bf + 2);
            }
            float2 sA = *(const float2*)(ssc + nt * 8 + qc2);
            float2 sB = *(const float2*)(ssc + nt * 8 + 8 + qc2);
            m0 = fminf(m0, fminf(fminf(sA.x - 2.f * d0[0], sA.y - 2.f * d0[1]),
                                 fminf(sB.x - 2.f * d1[0], sB.y - 2.f * d1[1])));
            m8 = fminf(m8, fminf(fminf(sA.x - 2.f * d0[2], sA.y - 2.f * d0[3]),
                                 fminf(sB.x - 2.f * d1[2], sB.y - 2.f * d1[3])));
        }
        #pragma unroll
        for (int o = 1; o < 4; o <<= 1) {
            m0 = fminf(m0, __shfl_xor_sync(0xffffffffu, m0, o));
            m8 = fminf(m8, __shfl_xor_sync(0xffffffffu, m8, o));
        }
        float thr0 = m0 + MARGIN, thr8 = m8 + MARGIN;

        // ---- pass 2: recompute, collect candidates ----
        int c0[MAXC], c8[MAXC];
        int n0 = 0, n8 = 0; bool ov0 = false, ov8 = false;
        for (int nt = 0; nt < 64; nt += 2) {
            float d0[4] = {0.f, 0.f, 0.f, 0.f};
            float d1[4] = {0.f, 0.f, 0.f, 0.f};
            uint32_t brow = bbase + (uint32_t)(nt * 8 * B_STRIDE);
            #pragma unroll
            for (int kc = 0; kc < 4; kc++) {
                uint32_t bf[4];
                ldmx4(bf, brow + kc * 32);
                mma16816(d0, afr[kc], bf + 0);
                mma16816(d1, afr[kc], bf + 2);
            }
            float2 sA = *(const float2*)(ssc + nt * 8 + qc2);
            float2 sB = *(const float2*)(ssc + nt * 8 + 8 + qc2);
            int kA = nt * 8 + qc2, kB = nt * 8 + 8 + qc2;
            if (sA.x - 2.f * d0[0] <= thr0) { if (n0 < MAXC) c0[n0++] = kA;     else ov0 = true; }
            if (sA.y - 2.f * d0[1] <= thr0) { if (n0 < MAXC) c0[n0++] = kA + 1; else ov0 = true; }
            if (sA.x - 2.f * d0[2] <= thr8) { if (n8 < MAXC) c8[n8++] = kA;     else ov8 = true; }
            if (sA.y - 2.f * d0[3] <= thr8) { if (n8 < MAXC) c8[n8++] = kA + 1; else ov8 = true; }
            if (sB.x - 2.f * d1[0] <= thr0) { if (n0 < MAXC) c0[n0++] = kB;     else ov0 = true; }
            if (sB.y - 2.f * d1[1] <= thr0) { if (n0 < MAXC) c0[n0++] = kB + 1; else ov0 = true; }
            if (sB.x - 2.f * d1[2] <= thr8) { if (n8 < MAXC) c8[n8++] = kB;     else ov8 = true; }
            if (sB.y - 2.f * d1[3] <= thr8) { if (n8 < MAXC) c8[n8++] = kB + 1; else ov8 = true; }
        }

        // ---- exact recheck; x re-read from global (round-14 proven) ----
        int r0 = w * 16 + qr, r8 = r0 + 8;
        float bd0 = FLT_MAX, bd8 = FLT_MAX;
        int   bi0 = KCODES,  bi8 = KCODES;
        {
            const float* xg = in + (size_t)b * DCH * SPATIAL + s0 + r0;
            float x[DCH];
            #pragma unroll
            for (int j = 0; j < DCH; j++) x[j] = xg[(size_t)j * SPATIAL];
            float sx = 0.f;                        // frozen sequential order
            #pragma unroll
            for (int j = 0; j < DCH; j++) sx = fmaf(x[j], x[j], sx);
            if (!ov0) {
                for (int ci = 0; ci < n0; ci++) {
                    int k = c0[ci];
                    float d = exact_d(cb + (size_t)k * DCH, x, sx, ssc[k]);
                    if (d < bd0 || (d == bd0 && k < bi0)) { bd0 = d; bi0 = k; }
                }
            } else {   // rare: exact scan of this thread's own 128 k's
                for (int nt = 0; nt < 64; nt++) {
                    int k = nt * 8 + qc2;
                    float d = exact_d(cb + (size_t)k * DCH, x, sx, ssc[k]);
                    if (d < bd0) { bd0 = d; bi0 = k; }
                    d = exact_d(cb + (size_t)(k + 1) * DCH, x, sx, ssc[k + 1]);
                    if (d < bd0) { bd0 = d; bi0 = k + 1; }
                }
            }
        }
        {
            const float* xg = in + (size_t)b * DCH * SPATIAL + s0 + r8;
            float x[DCH];
            #pragma unroll
            for (int j = 0; j < DCH; j++) x[j] = xg[(size_t)j * SPATIAL];
            float sx = 0.f;
            #pragma unroll
            for (int j = 0; j < DCH; j++) sx = fmaf(x[j], x[j], sx);
            if (!ov8) {
                for (int ci = 0; ci < n8; ci++) {
                    int k = c8[ci];
                    float d = exact_d(cb + (size_t)k * DCH, x, sx, ssc[k]);
                    if (d < bd8 || (d == bd8 && k < bi8)) { bd8 = d; bi8 = k; }
                }
            } else {
                for (int nt = 0; nt < 64; nt++) {
                    int k = nt * 8 + qc2;
                    float d = exact_d(cb + (size_t)k * DCH, x, sx, ssc[k]);
                    if (d < bd8) { bd8 = d; bi8 = k; }
                    d = exact_d(cb + (size_t)(k + 1) * DCH, x, sx, ssc[k + 1]);
                    if (d < bd8) { bd8 = d; bi8 = k + 1; }
                }
            }
        }
        // quad combine with first-min (smallest-k) tie-break
        #pragma unroll
        for (int o = 1; o < 4; o <<= 1) {
            float od = __shfl_xor_sync(0xffffffffu, bd0, o);
            int   oi = __shfl_xor_sync(0xffffffffu, bi0, o);
            if (od < bd0 || (od == bd0 && oi < bi0)) { bd0 = od; bi0 = oi; }
            od = __shfl_xor_sync(0xffffffffu, bd8, o);
            oi = __shfl_xor_sync(0xffffffffu, bi8, o);
            if (od < bd8 || (od == bd8 && oi < bi8)) { bd8 = od; bi8 = oi; }
        }
        if ((lane & 3) == 0) {
            sbidx[r0] = bi0;
            sbidx[r8] = bi8;
            out[IDX_OFF + v0 + r0] = (float)bi0;
            out[IDX_OFF + v0 + r8] = (float)bi8;
        }
        __syncthreads();

        // ---- epilogue: thread -> row dv, half h; STE store x + (c - x) ----
        {
            int bidx = sbidx[dv];
            const float* crow = cb + (size_t)bidx * DCH + h * 32;
            const float* xg = in + (size_t)b * DCH * SPATIAL + s0 + dv
                            + (size_t)h * 32 * SPATIAL;
            float* qout = out + (size_t)b * DCH * SPATIAL + s0 + dv
                        + (size_t)h * 32 * SPATIAL;
            #pragma unroll
            for (int q4 = 0; q4 < 8; q4++) {
                float4 c = *(const float4*)(crow + q4 * 4);
                float xv, dd;
                xv = xg[(size_t)(q4 * 4 + 0) * SPATIAL]; dd = c.x - xv;
                qout[(size_t)(q4 * 4 + 0) * SPATIAL] = xv + dd; threadLoss = fmaf(dd, dd, threadLoss);
                xv = xg[(size_t)(q4 * 4 + 1) * SPATIAL]; dd = c.y - xv;
                qout[(size_t)(q4 * 4 + 1) * SPATIAL] = xv + dd; threadLoss = fmaf(dd, dd, threadLoss);
                xv = xg[(size_t)(q4 * 4 + 2) * SPATIAL]; dd = c.z - xv;
                qout[(size_t)(q4 * 4 + 2) * SPATIAL] = xv + dd; threadLoss = fmaf(dd, dd, threadLoss);
                xv = xg[(size_t)(q4 * 4 + 3) * SPATIAL]; dd = c.w - xv;
                qout[(size_t)(q4 * 4 + 3) * SPATIAL] = xv + dd; threadLoss = fmaf(dd, dd, threadLoss);
            }
        }
        __syncthreads();   // protect A before next fill
    }

    // ---- loss reduction ----
    float ws = warpReduceSum(threadLoss);
    if (lane == 0) sloss[w] = ws;
    __syncthreads();
    if (tid == 0) {
        double t = 0.0;
        for (int i = 0; i < 8; i++) t += (double)sloss[i];
        g_blocksums[blockIdx.x] = t;
    }
}

__global__ void vq_finalize(float* __restrict__ out) {
    if (threadIdx.x == 0 && blockIdx.x == 0) {
        double t = 0.0;
        for (int i = 0; i < GRID_MAIN; i++) t += g_blocksums[i];
        out[LOSS_OFF] = (float)(1.25 * t / (double)Q_ELEMS);
    }
}

__global__ void vq_nop() {}

extern "C" void kernel_launch(void* const* d_in, const int* in_sizes, int n_in,
                              void* d_out, int out_size) {
    const float* in = (const float*)d_in[0];
    const float* cb = (const float*)d_in[1];
    float* out = (float*)d_out;

    static bool attr_set = false;
    if (!attr_set) {
        cudaFuncSetAttribute(vq_hmma, cudaFuncAttributeMaxDynamicSharedMemorySize, SM_TOTAL);
        attr_set = true;
    }

    vq_nop<<<1, 32>>>();
    vq_nop<<<1, 32>>>();
    vq_nop<<<1, 32>>>();
    vq_hmma<<<GRID_MAIN, BLOCK_MAIN, SM_TOTAL>>>(in, cb, out);
    vq_finalize<<<1, 32>>>(out);
}